// round 13
// baseline (speedup 1.0000x reference)
#include <cuda_runtime.h>
#include <math.h>

typedef unsigned long long ull;

#define NUM_PRIORS  3000
#define NUM_CLASSES 21
#define TOP_K       200
#define BATCH       256
#define TPB         512
#define KSLOT       6          // ceil(3000/512)
#define CAP         512        // fast-path candidate capacity (power of 2)
#define TARGET      448u       // selection target (<= CAP)
#define CONF_THRESH 0.01f
#define NMS_THRESH  0.45f
#define FULLM       0xffffffffu
#define NBC         (BATCH * (NUM_CLASSES - 1))

__device__ unsigned g_flag[NBC];

// identical arithmetic to all previously passing kernels' IoU test
__device__ __forceinline__ bool overlaps(float4 A, float aA, float4 B, float aB)
{
    float ltx = fmaxf(A.x, B.x);
    float lty = fmaxf(A.y, B.y);
    float rbx = fminf(A.z, B.z);
    float rby = fminf(A.w, B.w);
    float iw  = fmaxf(rbx - ltx, 0.f);
    float ih  = fmaxf(rby - lty, 0.f);
    float inter = iw * ih;
    float uni   = aA + aB - inter;
    return inter > NMS_THRESH * uni;
}

// warp-0 helper: over a 256-bin histogram, find the largest bin B such that
// cum(B) = sum_{x>=B} hist[x] >= tgt. Writes misc[0]=B, misc[1]=cum(B+1)
// (count strictly above bin B). Lane 0 writes misc[2] = total (always).
__device__ __forceinline__ void find_bin(const unsigned* hist, unsigned tgt,
                                         unsigned* misc, int lane)
{
    unsigned h[8];
    unsigned s = 0;
    #pragma unroll
    for (int i = 0; i < 8; i++) { h[i] = hist[lane * 8 + i]; s += h[i]; }
    unsigned suf = s;                      // inclusive suffix sum across lanes
    #pragma unroll
    for (int off = 1; off < 32; off <<= 1) {
        unsigned o = __shfl_down_sync(FULLM, suf, off);
        if (lane + off < 32) suf += o;
    }
    unsigned sufnext = __shfl_down_sync(FULLM, suf, 1);
    if (lane == 31) sufnext = 0;
    if (lane == 0) misc[2] = suf;          // total
    if (suf >= tgt && sufnext < tgt) {     // unique crossing lane
        unsigned run = sufnext;
        #pragma unroll
        for (int i = 7; i >= 0; i--) {
            unsigned nr = run + h[i];
            if (nr >= tgt) { misc[0] = (unsigned)(lane * 8 + i); misc[1] = run; break; }
            run = nr;
        }
    }
}

// one bitonic stage (k = KK) over 512 elements, 1 slot/thread, TPB=512.
template<unsigned KK>
__device__ __forceinline__ void sort_stage512(ull& K, ull* keys, unsigned t)
{
    bool d0 = ((t & KK) == 0u);            // for KK=512: always true (descending)
    if constexpr (KK >= 64u) {             // shared phases j in [32, min(KK/2,256)]
        keys[t] = K;
        __syncthreads();
        constexpr unsigned JS = (KK / 2u < 256u) ? KK / 2u : 256u;
        #pragma unroll
        for (unsigned j = JS; j >= 32u; j >>= 1) {
            unsigned ixj = t ^ j;
            if (ixj > t) {
                ull a = keys[t], b = keys[ixj];
                bool desc = ((t & KK) == 0u);
                if (desc ? (a < b) : (a > b)) { keys[t] = b; keys[ixj] = a; }
            }
            __syncthreads();
        }
        K = keys[t];
    }
    {                                       // shfl phases j <= 16
        constexpr unsigned JT = (KK / 2u < 16u) ? KK / 2u : 16u;
        #pragma unroll
        for (unsigned j = JT; j >= 1u; j >>= 1) {
            bool lower = ((t & j) == 0u);
            ull mine = K;
            ull oth  = __shfl_xor_sync(FULLM, mine, j);
            bool keepmax = (lower == d0);
            bool mg = mine > oth;
            K = keepmax ? (mg ? mine : oth) : (mg ? oth : mine);
        }
    }
}

// ---------------------------------------------------------------------------
// Fast path: exact radix-select top-[448,512] -> sort 512 -> ordered scan.
// Zeroes its own residual tail rows (and the background block for cls==1).
// ---------------------------------------------------------------------------
__global__ void __launch_bounds__(TPB, 3)
nms_fast_kernel(const float* __restrict__ loc_data,
                const float* __restrict__ conf_data,
                const float* __restrict__ priors,
                float* __restrict__ out)
{
    __shared__ ull      buf[CAP];        // 4 KB keys
    __shared__ float4   sbox[CAP];       // 8 KB decoded boxes
    __shared__ float4   accb[TOP_K];
    __shared__ float    acca[TOP_K];
    __shared__ unsigned hist[256];
    __shared__ unsigned hist2[256];      // mantissa-pass histogram (no re-zero)
    __shared__ unsigned ovrT[32];
    __shared__ unsigned badp[16];
    __shared__ unsigned misc[4];
    __shared__ int      scnt;

    const int bc   = blockIdx.x;
    const int b    = bc / (NUM_CLASSES - 1);
    const int cls  = bc % (NUM_CLASSES - 1) + 1;
    const unsigned t = threadIdx.x;
    const int lane = t & 31;
    const int g    = t >> 5;

    const float*  confb = conf_data + ((size_t)b * NUM_PRIORS) * NUM_CLASSES + cls;
    const float4* locb  = (const float4*)loc_data + (size_t)b * NUM_PRIORS;
    const float4* pri   = (const float4*)priors;

    // ---- keys + exponent histogram -------------------------------------
    if (t < 256) { hist[t] = 0u; hist2[t] = 0u; }
    if (t == 0) scnt = 0;
    __syncthreads();

    ull K[KSLOT];
    #pragma unroll
    for (int s = 0; s < KSLOT; s++) {
        int e = s * TPB + (int)t;
        unsigned sb = 0u;
        if (e < NUM_PRIORS) {
            float sc = confb[(size_t)e * NUM_CLASSES];
            if (sc > CONF_THRESH) sb = __float_as_uint(sc);
        }
        K[s] = ((ull)sb << 32) | (unsigned)(~e);
        if (sb) atomicAdd(&hist[sb >> 23], 1u);
    }
    __syncthreads();

    if (t < 32) find_bin(hist, TARGET, misc, lane);
    __syncthreads();

    const unsigned total = misc[2];
    bool overflow = false;
    unsigned T = 0u;

    if (total > CAP) {
        const unsigned E    = misc[0];
        const unsigned cntA = misc[1];
        #pragma unroll
        for (int s = 0; s < KSLOT; s++) {
            unsigned sb = (unsigned)(K[s] >> 32);
            if (sb && (sb >> 23) == E) atomicAdd(&hist2[(sb >> 15) & 0xFFu], 1u);
        }
        __syncthreads();
        if (t < 32) find_bin(hist2, TARGET - cntA, misc, lane);
        __syncthreads();
        const unsigned M = misc[0];
        unsigned sel_est = cntA + misc[1] + hist2[M];
        if (sel_est > CAP) overflow = true;
        else T = (E << 23) | (M << 15);
    }

    unsigned needslow = 1u;
    int nacc = 0;
    float* orow = out + ((size_t)b * NUM_CLASSES + cls) * TOP_K * 5;

    if (!overflow) {
        // ---- warp-aggregated compaction of selected keys ---------------
        #pragma unroll
        for (int s = 0; s < KSLOT; s++) {
            unsigned sb = (unsigned)(K[s] >> 32);
            bool sel = (sb != 0u) && (sb >= T);
            unsigned bm = __ballot_sync(FULLM, sel);
            int base = 0;
            if (lane == 0 && bm) base = atomicAdd(&scnt, __popc(bm));
            base = __shfl_sync(FULLM, base, 0);
            if (sel) {
                int pos = base + __popc(bm & ((1u << lane) - 1u));
                buf[pos] = K[s];           // !overflow guarantees pos < CAP
            }
        }
        __syncthreads();
        const unsigned selected = (unsigned)scnt;
        if (t >= selected) buf[t] = 0ull;
        __syncthreads();

        // ---- fully-unrolled bitonic sort of 512 (descending) -----------
        ull S = buf[t];
        sort_stage512<2u>(S, buf, t);
        sort_stage512<4u>(S, buf, t);
        sort_stage512<8u>(S, buf, t);
        sort_stage512<16u>(S, buf, t);
        sort_stage512<32u>(S, buf, t);
        sort_stage512<64u>(S, buf, t);
        sort_stage512<128u>(S, buf, t);
        sort_stage512<256u>(S, buf, t);
        sort_stage512<512u>(S, buf, t);
        buf[t] = S;

        // ---- decode selected boxes -------------------------------------
        {
            unsigned sb = (unsigned)(S >> 32);
            float4 bb = make_float4(0.f, 0.f, 0.f, 0.f);
            if (sb) {
                int idx = (int)~(unsigned)S;
                float4 l = locb[idx];
                float4 p = pri[idx];
                float cx = p.x + l.x * 0.1f * p.z;
                float cy = p.y + l.y * 0.1f * p.w;
                float w  = p.z * expf(l.z * 0.2f);
                float h  = p.w * expf(l.w * 0.2f);
                bb = make_float4(cx - w * 0.5f, cy - h * 0.5f,
                                 cx + w * 0.5f, cy + h * 0.5f);
            }
            sbox[t] = bb;
        }
        __syncthreads();

        // ---- windowed sequential-acceptance scan -----------------------
        // (next window's candidate data prefetched before the resolution
        //  barrier so LDS latency overlaps warp-0's serial work)
        int cursor = 0;
        ull      kk  = buf[lane];
        float4   cb  = sbox[lane];
        float4   pb1 = sbox[g];
        float4   pb2 = sbox[g + 16];
        for (;;) {
            unsigned sb = (unsigned)(kk >> 32);
            bool valid = (sb != 0u);
            float  car = (cb.z - cb.x) * (cb.w - cb.y);

            bool bad = false;
            for (int a = g; a < nacc; a += 16)
                if (overlaps(accb[a], acca[a], cb, car)) { bad = true; break; }
            unsigned badb = __ballot_sync(FULLM, bad && valid);
            if (lane == 0) badp[g] = badb;

            unsigned valmask = __ballot_sync(FULLM, valid);
            float  a1 = (pb1.z - pb1.x) * (pb1.w - pb1.y);
            unsigned ov1 = __ballot_sync(FULLM, (lane > g) && overlaps(pb1, a1, cb, car));
            float  a2 = (pb2.z - pb2.x) * (pb2.w - pb2.y);
            unsigned ov2 = __ballot_sync(FULLM, (lane > g + 16) && overlaps(pb2, a2, cb, car));
            if (lane == 0) { ovrT[g] = ov1; ovrT[g + 16] = ov2; }

            // prefetch next window while resolution runs
            int ncur = cursor + 32;
            ull    nkk  = 0ull;
            float4 ncb  = make_float4(0.f, 0.f, 0.f, 0.f);
            float4 npb1 = ncb, npb2 = ncb;
            if (ncur < CAP) {
                nkk  = buf[ncur + lane];
                ncb  = sbox[ncur + lane];
                npb1 = sbox[ncur + g];
                npb2 = sbox[ncur + g + 16];
            }
            __syncthreads();

            if (t < 32) {
                unsigned myOvrT = ovrT[lane];
                unsigned bm = (lane < 16) ? badp[lane] : 0u;
                unsigned badmask = __reduce_or_sync(FULLM, bm);
                unsigned avail = valmask & ~badmask;
                unsigned m = 0; int cnt = 0; int lim = TOP_K - nacc;
                while (avail && cnt < lim) {
                    int i = __ffs(avail) - 1;
                    m |= 1u << i; cnt++;
                    unsigned ov = __shfl_sync(FULLM, myOvrT, i);
                    avail &= ~ov;
                    avail &= ~(1u << i);
                }
                if ((m >> lane) & 1u) {
                    int slot = nacc + __popc(m & ((1u << lane) - 1u));
                    accb[slot] = cb;
                    acca[slot] = car;
                    float* r = orow + slot * 5;
                    r[0] = __uint_as_float(sb);
                    r[1] = cb.x; r[2] = cb.y; r[3] = cb.z; r[4] = cb.w;
                }
                if (t == 0) {
                    misc[0] = m;
                    misc[1] = (valmask != FULLM) ? 1u : 0u;
                }
            }
            __syncthreads();

            unsigned m = misc[0];
            unsigned dn = misc[1];
            nacc   += __popc(m);
            cursor  = ncur;
            if (dn || nacc >= TOP_K || cursor >= CAP) break;
            kk = nkk; cb = ncb; pb1 = npb1; pb2 = npb2;
        }
        needslow = (nacc < TOP_K && total > selected) ? 1u : 0u;
    }
    if (t == 0) g_flag[bc] = needslow;

    // ---- zero residual tail rows (only when this CTA's result is final) --
    if (needslow == 0u) {
        for (int j = nacc * 5 + (int)t; j < TOP_K * 5; j += TPB)
            orow[j] = 0.f;
    }
    // ---- zero the background (class 0) block once per batch --------------
    if (cls == 1) {
        float2* bg = (float2*)(out + (size_t)b * NUM_CLASSES * TOP_K * 5);
        if (t < TOP_K * 5 / 2) bg[t] = make_float2(0.f, 0.f);
    }
}

// ---------------------------------------------------------------------------
// Slow path (expected to run ~never): 20 blocks, each covering 256 (b,c)
// pairs with one coalesced flag read + syncthreads_or early exit. Flagged
// pairs run the proven R1 register-argmax NMS.
// ---------------------------------------------------------------------------
#define STPB 256
#define SKPT 12
#define SLOW_GRID (NBC / STPB)   // 20
__global__ void __launch_bounds__(STPB, 2)
nms_slow_kernel(const float* __restrict__ loc_data,
                const float* __restrict__ conf_data,
                const float* __restrict__ priors,
                float* __restrict__ out)
{
    const int base = blockIdx.x * STPB;
    const int tid  = threadIdx.x;

    // one coalesced probe; whole block exits if nothing flagged in its range
    unsigned myflag = g_flag[base + tid];
    if (!__syncthreads_or((int)myflag)) return;

    __shared__ float  s_ps[STPB / 32];
    __shared__ int    s_pe[STPB / 32];
    __shared__ float4 s_box;

    const int warp = tid >> 5;
    const int lane = tid & 31;
    const float NEG = -INFINITY;

    for (int bc = base; bc < base + STPB; bc++) {
        if (g_flag[bc] == 0u) continue;
        __syncthreads();   // protect shared reuse across bc iterations

        const int b = bc / (NUM_CLASSES - 1);
        const int c = bc % (NUM_CLASSES - 1) + 1;

        float sc[SKPT], bx1[SKPT], by1[SKPT], bx2[SKPT], by2[SKPT], ar[SKPT];
        const float4* locb  = (const float4*)loc_data + (size_t)b * NUM_PRIORS;
        const float4* pri   = (const float4*)priors;
        const float*  confb = conf_data + (size_t)b * NUM_PRIORS * NUM_CLASSES + c;

        #pragma unroll
        for (int k = 0; k < SKPT; k++) {
            int e = k * STPB + tid;
            if (e < NUM_PRIORS) {
                float4 l = locb[e];
                float4 p = pri[e];
                float cx = p.x + l.x * 0.1f * p.z;
                float cy = p.y + l.y * 0.1f * p.w;
                float w  = p.z * expf(l.z * 0.2f);
                float h  = p.w * expf(l.w * 0.2f);
                bx1[k] = cx - w * 0.5f; by1[k] = cy - h * 0.5f;
                bx2[k] = cx + w * 0.5f; by2[k] = cy + h * 0.5f;
                ar[k]  = (bx2[k] - bx1[k]) * (by2[k] - by1[k]);
                float s = confb[(size_t)e * NUM_CLASSES];
                sc[k] = (s > CONF_THRESH) ? s : NEG;
            } else {
                sc[k] = NEG; bx1[k] = by1[k] = bx2[k] = by2[k] = 0.f; ar[k] = 0.f;
            }
        }

        float* orow = out + ((size_t)b * NUM_CLASSES + c) * TOP_K * 5;
        int it_end = TOP_K;

        for (int it = 0; it < TOP_K; it++) {
            float ls = sc[0]; int lk = 0;
            #pragma unroll
            for (int k = 1; k < SKPT; k++)
                if (sc[k] > ls) { ls = sc[k]; lk = k; }
            int le = lk * STPB + tid;
            #pragma unroll
            for (int off = 16; off; off >>= 1) {
                float os = __shfl_xor_sync(FULLM, ls, off);
                int   oe = __shfl_xor_sync(FULLM, le, off);
                if (os > ls || (os == ls && oe < le)) { ls = os; le = oe; }
            }
            if (lane == 0) { s_ps[warp] = ls; s_pe[warp] = le; }
            __syncthreads();
            float bs = s_ps[0]; int be = s_pe[0];
            #pragma unroll
            for (int w = 1; w < STPB / 32; w++) {
                float os = s_ps[w]; int oe = s_pe[w];
                if (os > bs || (os == bs && oe < be)) { bs = os; be = oe; }
            }
            if (!(bs > CONF_THRESH)) { it_end = it; break; }
            if (tid == (be & (STPB - 1))) {
                int k = be >> 8;
                s_box = make_float4(bx1[k], by1[k], bx2[k], by2[k]);
                sc[k] = NEG;
                float* r = orow + it * 5;
                r[0] = bs; r[1] = bx1[k]; r[2] = by1[k]; r[3] = bx2[k]; r[4] = by2[k];
            }
            __syncthreads();
            float4 B  = s_box;
            float  A1 = (B.z - B.x) * (B.w - B.y);
            #pragma unroll
            for (int k = 0; k < SKPT; k++) {
                float ltx = fmaxf(B.x, bx1[k]);
                float lty = fmaxf(B.y, by1[k]);
                float rbx = fminf(B.z, bx2[k]);
                float rby = fminf(B.w, by2[k]);
                float iw  = fmaxf(rbx - ltx, 0.f);
                float ih  = fmaxf(rby - lty, 0.f);
                float inter = iw * ih;
                float uni   = A1 + ar[k] - inter;
                if (inter > NMS_THRESH * uni) sc[k] = NEG;
            }
        }
        // zero tail rows for this block
        for (int j = it_end * 5 + tid; j < TOP_K * 5; j += STPB)
            orow[j] = 0.f;
        __syncthreads();
    }
}

extern "C" void kernel_launch(void* const* d_in, const int* in_sizes, int n_in,
                              void* d_out, int out_size)
{
    const float* loc_data  = (const float*)d_in[0];
    const float* conf_data = (const float*)d_in[1];
    const float* priors    = (const float*)d_in[2];
    float* out = (float*)d_out;

    nms_fast_kernel<<<NBC, TPB>>>(loc_data, conf_data, priors, out);
    nms_slow_kernel<<<SLOW_GRID, STPB>>>(loc_data, conf_data, priors, out);
}

// round 14
// speedup vs baseline: 1.0554x; 1.0554x over previous
#include <cuda_runtime.h>
#include <math.h>

typedef unsigned long long ull;

#define NUM_PRIORS  3000
#define NUM_CLASSES 21
#define TOP_K       200
#define BATCH       256
#define TPB         512
#define KSLOT       6          // ceil(3000/512)
#define CAP         512        // fast-path candidate capacity (power of 2)
#define TARGET      448u       // selection target (<= CAP)
#define CONF_THRESH 0.01f
#define NMS_THRESH  0.45f
#define FULLM       0xffffffffu
#define NBC         (BATCH * (NUM_CLASSES - 1))

__device__ unsigned g_flag[NBC];

// identical arithmetic to all previously passing kernels' IoU test
__device__ __forceinline__ bool overlaps(float4 A, float aA, float4 B, float aB)
{
    float ltx = fmaxf(A.x, B.x);
    float lty = fmaxf(A.y, B.y);
    float rbx = fminf(A.z, B.z);
    float rby = fminf(A.w, B.w);
    float iw  = fmaxf(rbx - ltx, 0.f);
    float ih  = fmaxf(rby - lty, 0.f);
    float inter = iw * ih;
    float uni   = aA + aB - inter;
    return inter > NMS_THRESH * uni;
}

// warp-0 helper: over a 256-bin histogram, find the largest bin B such that
// cum(B) = sum_{x>=B} hist[x] >= tgt. Writes misc[0]=B, misc[1]=cum(B+1)
// (count strictly above bin B). Lane 0 writes misc[2] = total (always).
__device__ __forceinline__ void find_bin(const unsigned* hist, unsigned tgt,
                                         unsigned* misc, int lane)
{
    unsigned h[8];
    unsigned s = 0;
    #pragma unroll
    for (int i = 0; i < 8; i++) { h[i] = hist[lane * 8 + i]; s += h[i]; }
    unsigned suf = s;                      // inclusive suffix sum across lanes
    #pragma unroll
    for (int off = 1; off < 32; off <<= 1) {
        unsigned o = __shfl_down_sync(FULLM, suf, off);
        if (lane + off < 32) suf += o;
    }
    unsigned sufnext = __shfl_down_sync(FULLM, suf, 1);
    if (lane == 31) sufnext = 0;
    if (lane == 0) misc[2] = suf;          // total
    if (suf >= tgt && sufnext < tgt) {     // unique crossing lane
        unsigned run = sufnext;
        #pragma unroll
        for (int i = 7; i >= 0; i--) {
            unsigned nr = run + h[i];
            if (nr >= tgt) { misc[0] = (unsigned)(lane * 8 + i); misc[1] = run; break; }
            run = nr;
        }
    }
}

// one bitonic stage (k = KK) over 512 elements, 1 slot/thread, TPB=512.
template<unsigned KK>
__device__ __forceinline__ void sort_stage512(ull& K, ull* keys, unsigned t)
{
    bool d0 = ((t & KK) == 0u);            // for KK=512: always true (descending)
    if constexpr (KK >= 64u) {             // shared phases j in [32, min(KK/2,256)]
        keys[t] = K;
        __syncthreads();
        constexpr unsigned JS = (KK / 2u < 256u) ? KK / 2u : 256u;
        #pragma unroll
        for (unsigned j = JS; j >= 32u; j >>= 1) {
            unsigned ixj = t ^ j;
            if (ixj > t) {
                ull a = keys[t], b = keys[ixj];
                bool desc = ((t & KK) == 0u);
                if (desc ? (a < b) : (a > b)) { keys[t] = b; keys[ixj] = a; }
            }
            __syncthreads();
        }
        K = keys[t];
    }
    {                                       // shfl phases j <= 16
        constexpr unsigned JT = (KK / 2u < 16u) ? KK / 2u : 16u;
        #pragma unroll
        for (unsigned j = JT; j >= 1u; j >>= 1) {
            bool lower = ((t & j) == 0u);
            ull mine = K;
            ull oth  = __shfl_xor_sync(FULLM, mine, j);
            bool keepmax = (lower == d0);
            bool mg = mine > oth;
            K = keepmax ? (mg ? mine : oth) : (mg ? oth : mine);
        }
    }
}

// ---------------------------------------------------------------------------
// Fast path: exact radix-select top-[448,512] -> sort 512 -> ordered scan.
// Zeroes its own residual tail rows (and the background block for cls==1).
// (byte-identical to the 420.6us R12 version)
// ---------------------------------------------------------------------------
__global__ void __launch_bounds__(TPB, 3)
nms_fast_kernel(const float* __restrict__ loc_data,
                const float* __restrict__ conf_data,
                const float* __restrict__ priors,
                float* __restrict__ out)
{
    __shared__ ull      buf[CAP];        // 4 KB keys
    __shared__ float4   sbox[CAP];       // 8 KB decoded boxes
    __shared__ float4   accb[TOP_K];
    __shared__ float    acca[TOP_K];
    __shared__ unsigned hist[256];
    __shared__ unsigned ovrT[32];
    __shared__ unsigned badp[16];
    __shared__ unsigned misc[4];
    __shared__ int      scnt;

    const int bc   = blockIdx.x;
    const int b    = bc / (NUM_CLASSES - 1);
    const int cls  = bc % (NUM_CLASSES - 1) + 1;
    const unsigned t = threadIdx.x;
    const int lane = t & 31;
    const int g    = t >> 5;

    const float*  confb = conf_data + ((size_t)b * NUM_PRIORS) * NUM_CLASSES + cls;
    const float4* locb  = (const float4*)loc_data + (size_t)b * NUM_PRIORS;
    const float4* pri   = (const float4*)priors;

    // ---- keys + exponent histogram -------------------------------------
    if (t < 256) hist[t] = 0u;
    if (t == 0) scnt = 0;
    __syncthreads();

    ull K[KSLOT];
    #pragma unroll
    for (int s = 0; s < KSLOT; s++) {
        int e = s * TPB + (int)t;
        unsigned sb = 0u;
        if (e < NUM_PRIORS) {
            float sc = confb[(size_t)e * NUM_CLASSES];
            if (sc > CONF_THRESH) sb = __float_as_uint(sc);
        }
        K[s] = ((ull)sb << 32) | (unsigned)(~e);
        if (sb) atomicAdd(&hist[sb >> 23], 1u);
    }
    __syncthreads();

    if (t < 32) find_bin(hist, TARGET, misc, lane);
    __syncthreads();

    const unsigned total = misc[2];
    bool overflow = false;
    unsigned T = 0u;

    if (total > CAP) {
        const unsigned E    = misc[0];
        const unsigned cntA = misc[1];
        __syncthreads();                   // find_bin's hist reads done
        if (t < 256) hist[t] = 0u;
        __syncthreads();
        #pragma unroll
        for (int s = 0; s < KSLOT; s++) {
            unsigned sb = (unsigned)(K[s] >> 32);
            if (sb && (sb >> 23) == E) atomicAdd(&hist[(sb >> 15) & 0xFFu], 1u);
        }
        __syncthreads();
        if (t < 32) find_bin(hist, TARGET - cntA, misc, lane);
        __syncthreads();
        const unsigned M = misc[0];
        unsigned sel_est = cntA + misc[1] + hist[M];
        if (sel_est > CAP) overflow = true;
        else T = (E << 23) | (M << 15);
    }

    unsigned needslow = 1u;
    int nacc = 0;
    float* orow = out + ((size_t)b * NUM_CLASSES + cls) * TOP_K * 5;

    if (!overflow) {
        // ---- warp-aggregated compaction of selected keys ---------------
        #pragma unroll
        for (int s = 0; s < KSLOT; s++) {
            unsigned sb = (unsigned)(K[s] >> 32);
            bool sel = (sb != 0u) && (sb >= T);
            unsigned bm = __ballot_sync(FULLM, sel);
            int base = 0;
            if (lane == 0 && bm) base = atomicAdd(&scnt, __popc(bm));
            base = __shfl_sync(FULLM, base, 0);
            if (sel) {
                int pos = base + __popc(bm & ((1u << lane) - 1u));
                buf[pos] = K[s];           // !overflow guarantees pos < CAP
            }
        }
        __syncthreads();
        const unsigned selected = (unsigned)scnt;
        if (t >= selected) buf[t] = 0ull;
        __syncthreads();

        // ---- fully-unrolled bitonic sort of 512 (descending) -----------
        ull S = buf[t];
        sort_stage512<2u>(S, buf, t);
        sort_stage512<4u>(S, buf, t);
        sort_stage512<8u>(S, buf, t);
        sort_stage512<16u>(S, buf, t);
        sort_stage512<32u>(S, buf, t);
        sort_stage512<64u>(S, buf, t);
        sort_stage512<128u>(S, buf, t);
        sort_stage512<256u>(S, buf, t);
        sort_stage512<512u>(S, buf, t);
        buf[t] = S;

        // ---- decode selected boxes -------------------------------------
        {
            unsigned sb = (unsigned)(S >> 32);
            float4 bb = make_float4(0.f, 0.f, 0.f, 0.f);
            if (sb) {
                int idx = (int)~(unsigned)S;
                float4 l = locb[idx];
                float4 p = pri[idx];
                float cx = p.x + l.x * 0.1f * p.z;
                float cy = p.y + l.y * 0.1f * p.w;
                float w  = p.z * expf(l.z * 0.2f);
                float h  = p.w * expf(l.w * 0.2f);
                bb = make_float4(cx - w * 0.5f, cy - h * 0.5f,
                                 cx + w * 0.5f, cy + h * 0.5f);
            }
            sbox[t] = bb;
        }
        __syncthreads();

        // ---- windowed sequential-acceptance scan -----------------------
        int cursor = 0;
        for (;;) {
            int ci = cursor + lane;
            ull kk = buf[ci];
            unsigned sb = (unsigned)(kk >> 32);
            bool valid = (sb != 0u);
            float4 cb = sbox[ci];
            float  car = (cb.z - cb.x) * (cb.w - cb.y);

            bool bad = false;
            for (int a = g; a < nacc; a += 16)
                if (overlaps(accb[a], acca[a], cb, car)) { bad = true; break; }
            unsigned badb = __ballot_sync(FULLM, bad && valid);
            if (lane == 0) badp[g] = badb;

            unsigned valmask = __ballot_sync(FULLM, valid);
            float4 b1 = sbox[cursor + g];
            float  a1 = (b1.z - b1.x) * (b1.w - b1.y);
            unsigned ov1 = __ballot_sync(FULLM, (lane > g) && overlaps(b1, a1, cb, car));
            float4 b2 = sbox[cursor + g + 16];
            float  a2 = (b2.z - b2.x) * (b2.w - b2.y);
            unsigned ov2 = __ballot_sync(FULLM, (lane > g + 16) && overlaps(b2, a2, cb, car));
            if (lane == 0) { ovrT[g] = ov1; ovrT[g + 16] = ov2; }
            __syncthreads();

            if (t < 32) {
                unsigned myOvrT = ovrT[lane];
                unsigned bm = (lane < 16) ? badp[lane] : 0u;
                unsigned badmask = __reduce_or_sync(FULLM, bm);
                unsigned avail = valmask & ~badmask;
                unsigned m = 0; int cnt = 0; int lim = TOP_K - nacc;
                while (avail && cnt < lim) {
                    int i = __ffs(avail) - 1;
                    m |= 1u << i; cnt++;
                    unsigned ov = __shfl_sync(FULLM, myOvrT, i);
                    avail &= ~ov;
                    avail &= ~(1u << i);
                }
                if ((m >> lane) & 1u) {
                    int slot = nacc + __popc(m & ((1u << lane) - 1u));
                    accb[slot] = cb;
                    acca[slot] = car;
                    float* r = orow + slot * 5;
                    r[0] = __uint_as_float(sb);
                    r[1] = cb.x; r[2] = cb.y; r[3] = cb.z; r[4] = cb.w;
                }
                if (t == 0) {
                    misc[0] = m;
                    misc[1] = (valmask != FULLM) ? 1u : 0u;
                }
            }
            __syncthreads();

            unsigned m = misc[0];
            unsigned dn = misc[1];
            nacc   += __popc(m);
            cursor += 32;
            if (dn || nacc >= TOP_K || cursor >= CAP) break;
        }
        needslow = (nacc < TOP_K && total > selected) ? 1u : 0u;
    }
    if (t == 0) g_flag[bc] = needslow;

    // ---- zero residual tail rows (only when this CTA's result is final) --
    if (needslow == 0u) {
        for (int j = nacc * 5 + (int)t; j < TOP_K * 5; j += TPB)
            orow[j] = 0.f;
    }
    // ---- zero the background (class 0) block once per batch --------------
    if (cls == 1) {
        float2* bg = (float2*)(out + (size_t)b * NUM_CLASSES * TOP_K * 5);
        if (t < TOP_K * 5 / 2) bg[t] = make_float2(0.f, 0.f);
    }
}

// ---------------------------------------------------------------------------
// Slow path (expected to run ~never): 20 blocks, each covering 256 (b,c)
// pairs with one coalesced flag read + syncthreads_or early exit. Flagged
// pairs run the proven R1 register-argmax NMS. (measured 4.4us in R13)
// ---------------------------------------------------------------------------
#define STPB 256
#define SKPT 12
#define SLOW_GRID (NBC / STPB)   // 20
__global__ void __launch_bounds__(STPB, 2)
nms_slow_kernel(const float* __restrict__ loc_data,
                const float* __restrict__ conf_data,
                const float* __restrict__ priors,
                float* __restrict__ out)
{
    const int base = blockIdx.x * STPB;
    const int tid  = threadIdx.x;

    // one coalesced probe; whole block exits if nothing flagged in its range
    unsigned myflag = g_flag[base + tid];
    if (!__syncthreads_or((int)myflag)) return;

    __shared__ float  s_ps[STPB / 32];
    __shared__ int    s_pe[STPB / 32];
    __shared__ float4 s_box;

    const int warp = tid >> 5;
    const int lane = tid & 31;
    const float NEG = -INFINITY;

    for (int bc = base; bc < base + STPB; bc++) {
        if (g_flag[bc] == 0u) continue;
        __syncthreads();   // protect shared reuse across bc iterations

        const int b = bc / (NUM_CLASSES - 1);
        const int c = bc % (NUM_CLASSES - 1) + 1;

        float sc[SKPT], bx1[SKPT], by1[SKPT], bx2[SKPT], by2[SKPT], ar[SKPT];
        const float4* locb  = (const float4*)loc_data + (size_t)b * NUM_PRIORS;
        const float4* pri   = (const float4*)priors;
        const float*  confb = conf_data + (size_t)b * NUM_PRIORS * NUM_CLASSES + c;

        #pragma unroll
        for (int k = 0; k < SKPT; k++) {
            int e = k * STPB + tid;
            if (e < NUM_PRIORS) {
                float4 l = locb[e];
                float4 p = pri[e];
                float cx = p.x + l.x * 0.1f * p.z;
                float cy = p.y + l.y * 0.1f * p.w;
                float w  = p.z * expf(l.z * 0.2f);
                float h  = p.w * expf(l.w * 0.2f);
                bx1[k] = cx - w * 0.5f; by1[k] = cy - h * 0.5f;
                bx2[k] = cx + w * 0.5f; by2[k] = cy + h * 0.5f;
                ar[k]  = (bx2[k] - bx1[k]) * (by2[k] - by1[k]);
                float s = confb[(size_t)e * NUM_CLASSES];
                sc[k] = (s > CONF_THRESH) ? s : NEG;
            } else {
                sc[k] = NEG; bx1[k] = by1[k] = bx2[k] = by2[k] = 0.f; ar[k] = 0.f;
            }
        }

        float* orow = out + ((size_t)b * NUM_CLASSES + c) * TOP_K * 5;
        int it_end = TOP_K;

        for (int it = 0; it < TOP_K; it++) {
            float ls = sc[0]; int lk = 0;
            #pragma unroll
            for (int k = 1; k < SKPT; k++)
                if (sc[k] > ls) { ls = sc[k]; lk = k; }
            int le = lk * STPB + tid;
            #pragma unroll
            for (int off = 16; off; off >>= 1) {
                float os = __shfl_xor_sync(FULLM, ls, off);
                int   oe = __shfl_xor_sync(FULLM, le, off);
                if (os > ls || (os == ls && oe < le)) { ls = os; le = oe; }
            }
            if (lane == 0) { s_ps[warp] = ls; s_pe[warp] = le; }
            __syncthreads();
            float bs = s_ps[0]; int be = s_pe[0];
            #pragma unroll
            for (int w = 1; w < STPB / 32; w++) {
                float os = s_ps[w]; int oe = s_pe[w];
                if (os > bs || (os == bs && oe < be)) { bs = os; be = oe; }
            }
            if (!(bs > CONF_THRESH)) { it_end = it; break; }
            if (tid == (be & (STPB - 1))) {
                int k = be >> 8;
                s_box = make_float4(bx1[k], by1[k], bx2[k], by2[k]);
                sc[k] = NEG;
                float* r = orow + it * 5;
                r[0] = bs; r[1] = bx1[k]; r[2] = by1[k]; r[3] = bx2[k]; r[4] = by2[k];
            }
            __syncthreads();
            float4 B  = s_box;
            float  A1 = (B.z - B.x) * (B.w - B.y);
            #pragma unroll
            for (int k = 0; k < SKPT; k++) {
                float ltx = fmaxf(B.x, bx1[k]);
                float lty = fmaxf(B.y, by1[k]);
                float rbx = fminf(B.z, bx2[k]);
                float rby = fminf(B.w, by2[k]);
                float iw  = fmaxf(rbx - ltx, 0.f);
                float ih  = fmaxf(rby - lty, 0.f);
                float inter = iw * ih;
                float uni   = A1 + ar[k] - inter;
                if (inter > NMS_THRESH * uni) sc[k] = NEG;
            }
        }
        // zero tail rows for this block
        for (int j = it_end * 5 + tid; j < TOP_K * 5; j += STPB)
            orow[j] = 0.f;
        __syncthreads();
    }
}

extern "C" void kernel_launch(void* const* d_in, const int* in_sizes, int n_in,
                              void* d_out, int out_size)
{
    const float* loc_data  = (const float*)d_in[0];
    const float* conf_data = (const float*)d_in[1];
    const float* priors    = (const float*)d_in[2];
    float* out = (float*)d_out;

    nms_fast_kernel<<<NBC, TPB>>>(loc_data, conf_data, priors, out);
    nms_slow_kernel<<<SLOW_GRID, STPB>>>(loc_data, conf_data, priors, out);
}